// round 8
// baseline (speedup 1.0000x reference)
#include <cuda_runtime.h>
#include <math.h>

#define TT 128
#define BB 32
#define EE 512
#define HH 512
#define UU 1024
#define VV 10000
#define G4 2048   // 4*H

// recurrence: 32 h-col tiles (16 cols) x 4 batch groups (8 b)   [R6 design]
#define NBLK 128
#define SMEM_LSTM (131072 + 32768 + 16384)   // Wt + hsd + Pp = 176KB

// ---------------- scratch (static device globals; no allocation) ----------------
__device__ __align__(128) float g_X1 [TT*G4*BB];   // pregates [t][g4][b]
__device__ __align__(128) float g_H1 [TT*BB*HH];
__device__ __align__(128) float g_S  [TT*BB*UU];
__device__ __align__(128) float g_CTX[TT*BB*HH];
__device__ __align__(128) float g_X2 [TT*G4*BB];   // pregates [t][g4][b]
__device__ __align__(128) float g_HS [TT*BB*HH];
__device__ __align__(128) float g_HT [2][4*512*8]; // parity h [bg][k][b8]
__device__ unsigned g_flag[NBLK];                  // [bg*32 + hc], monotonic

// ---------------- helpers ----------------
typedef unsigned long long ull;
__device__ __forceinline__ ull pack2(float x) {
    ull r;
    asm("mov.b64 %0, {%1, %1};" : "=l"(r) : "r"(__float_as_uint(x)));
    return r;
}
__device__ __forceinline__ void fma2(ull& d, ull a, ull b) {
    asm("fma.rn.f32x2 %0, %1, %2, %0;" : "+l"(d) : "l"(a), "l"(b));
}
__device__ __forceinline__ void unpack2(ull v, float& lo, float& hi) {
    unsigned a, b;
    asm("mov.b64 {%0, %1}, %2;" : "=r"(a), "=r"(b) : "l"(v));
    lo = __uint_as_float(a); hi = __uint_as_float(b);
}
__device__ __forceinline__ unsigned ld_acq(const unsigned* p) {
    unsigned v;
    asm volatile("ld.acquire.gpu.global.u32 %0, [%1];" : "=r"(v) : "l"(p));
    return v;
}
__device__ __forceinline__ void st_rel(unsigned* p, unsigned v) {
    asm volatile("st.release.gpu.global.u32 [%0], %1;" :: "l"(p), "r"(v) : "memory");
}
__device__ __forceinline__ float sigmoidf_(float x) { return 1.f / (1.f + expf(-x)); }

// ---------------- prep: reset flags, h0 -> g_HT[1] in [bg][k][b8] layout --------
__global__ void prep(const float* __restrict__ h0row)
{
    int tid = threadIdx.x;
    if (tid < NBLK) g_flag[tid] = 0;
    for (int idx = tid; idx < BB * HH; idx += 256) {
        int b = idx >> 9, h = idx & 511;
        g_HT[1][(b >> 3) * 4096 + h * 8 + (b & 7)] = h0row[idx];
    }
}

// ---------------- persistent LSTM recurrence (R6) -------------------------------
__global__ __launch_bounds__(256)
void lstm_seq(const float* __restrict__ XT,     // [T][G4][B] pregates
              const float* __restrict__ Whh,    // [G4][H]
              const float* __restrict__ c0row,  // [B][H]
              float* __restrict__ Hout)         // [T][B][H]
{
    extern __shared__ char smraw[];
    float* Wt  = (float*)smraw;                   // [512][64]
    ull*   hsd = (ull*)(smraw + 131072);          // [512][8] dup h
    ull*   Pp  = (ull*)(smraw + 131072 + 32768);  // [8][32][8] partials

    const int bid = blockIdx.x;
    const int tid = threadIdx.x;
    const int hc  = bid & 31;
    const int bg  = bid >> 5;

    for (int idx = tid; idx < 64 * 128; idx += 256) {
        int r  = idx & 63;
        int k4 = idx >> 6;
        int g = r >> 4, j = r & 15;
        int gr = g * 512 + 16 * hc + j;
        float4 w = *(const float4*)(Whh + (size_t)gr * HH + k4 * 4);
        Wt[(k4 * 4 + 0) * 64 + r] = w.x;
        Wt[(k4 * 4 + 1) * 64 + r] = w.y;
        Wt[(k4 * 4 + 2) * 64 + r] = w.z;
        Wt[(k4 * 4 + 3) * 64 + r] = w.w;
    }

    const int warp = tid >> 5;
    const int lane = tid & 31;
    const int rg   = lane >> 1;
    const int bq   = lane & 1;
    const int kbeg = warp * 64;

    const int j  = tid >> 3;
    const int bb = tid & 7;
    float cv = 0.f;
    if (tid < 128) cv = c0row[(8 * bg + bb) * HH + 16 * hc + j];

    unsigned* myflag = &g_flag[bid];
    const unsigned* grpflags = &g_flag[bg * 32];

    for (int t = 0; t < TT; t++) {
        if (t > 0) {
            if (tid < 32) {
                const unsigned* f = grpflags + tid;
                while (ld_acq(f) < (unsigned)t) { }
            }
        }
        __syncthreads();

        {
            const float4* src = (const float4*)&g_HT[(t + 1) & 1][bg * 4096];
            #pragma unroll
            for (int r = 0; r < 4; r++) {
                int i = tid + r * 256;
                float4 v = __ldcg(src + i);
                int k  = i >> 1;
                int b0 = (i & 1) * 4;
                ull* d = &hsd[k * 8 + b0];
                d[0] = pack2(v.x); d[1] = pack2(v.y);
                d[2] = pack2(v.z); d[3] = pack2(v.w);
            }
        }
        __syncthreads();

        ull acc[2][4];
        #pragma unroll
        for (int i = 0; i < 2; i++)
            #pragma unroll
            for (int q = 0; q < 4; q++) acc[i][q] = 0ull;

        #pragma unroll 4
        for (int k = kbeg; k < kbeg + 64; k++) {
            ulonglong2 wp = *(const ulonglong2*)&Wt[k * 64 + rg * 4];
            ulonglong2 hA = *(const ulonglong2*)&hsd[k * 8 + bq * 4];
            ulonglong2 hB = *(const ulonglong2*)&hsd[k * 8 + bq * 4 + 2];
            fma2(acc[0][0], wp.x, hA.x); fma2(acc[0][1], wp.x, hA.y);
            fma2(acc[0][2], wp.x, hB.x); fma2(acc[0][3], wp.x, hB.y);
            fma2(acc[1][0], wp.y, hA.x); fma2(acc[1][1], wp.y, hA.y);
            fma2(acc[1][2], wp.y, hB.x); fma2(acc[1][3], wp.y, hB.y);
        }

        {
            ull* pb = &Pp[((warp * 32) + rg * 2) * 8 + bq * 4];
            *(ulonglong2*)(pb + 0)  = make_ulonglong2(acc[0][0], acc[0][1]);
            *(ulonglong2*)(pb + 2)  = make_ulonglong2(acc[0][2], acc[0][3]);
            *(ulonglong2*)(pb + 8)  = make_ulonglong2(acc[1][0], acc[1][1]);
            *(ulonglong2*)(pb + 10) = make_ulonglong2(acc[1][2], acc[1][3]);
        }
        __syncthreads();

        if (tid < 128) {
            const float* pf = (const float*)Pp;
            float gate[4];
            #pragma unroll
            for (int g = 0; g < 4; g++) {
                int r  = g * 16 + j;
                int rp = r >> 1, ln = r & 1;
                float v = XT[((size_t)t * G4 + g * 512 + 16 * hc + j) * BB
                             + 8 * bg + bb];
                #pragma unroll
                for (int s = 0; s < 8; s++)
                    v += pf[((s * 32 + rp) * 8 + bb) * 2 + ln];
                gate[g] = v;
            }
            float gi = sigmoidf_(gate[0]);
            float gf = sigmoidf_(gate[1]);
            float gg = tanhf(gate[2]);
            float go = sigmoidf_(gate[3]);
            cv = gf * cv + gi * gg;
            float hv = go * tanhf(cv);
            Hout[(size_t)t * BB * HH + (8 * bg + bb) * HH + 16 * hc + j] = hv;
            g_HT[t & 1][bg * 4096 + (16 * hc + j) * 8 + bb] = hv;
        }

        __syncthreads();
        if (tid == 0) st_rel(myflag, (unsigned)(t + 1));
    }
}

// ---------------- f32x2 SGEMM  C = A(MxK) * B(NxK)^T + biases -------------------
// Block tile 128m x 64n, K-step 16, 256 threads, thread tile 8m x 4n (f32x2).
// B duplicated at smem-store time; A pairs native. transC stores [t][g4][b].
__global__ __launch_bounds__(256)
void sgemm_tn2(const float* __restrict__ A, const float* __restrict__ B,
               float* __restrict__ C,
               const float* __restrict__ bias1, const float* __restrict__ bias2,
               int M, int N, int K, int lda, int ldb, int ldc,
               long long aBS, long long bBS, long long cBS, int transC)
{
    __shared__ float As[16 * 128];   // As[k][m]
    __shared__ ull   Bd[16 * 64];    // Bd[k][n] duplicated pairs

    const int tid = threadIdx.x;
    const int tx = tid & 15;         // n-group (4 n)
    const int ty = tid >> 4;         // m-group (8 m = 4 pairs)
    const int m0 = blockIdx.y * 128;
    const int n0 = blockIdx.x * 64;

    const float* Ab = A + (long long)blockIdx.z * aBS;
    const float* Bb = B + (long long)blockIdx.z * bBS;
    float*       Cb = C + (long long)blockIdx.z * cBS;

    // load indices
    const int am = tid >> 1;            // 0..127 row
    const int ak = (tid & 1) * 8;       // k offset 0/8
    const int bn = tid >> 2;            // 0..63 B row (n)
    const int bk = (tid & 3) * 4;       // k offset

    ull acc[4][4];
    #pragma unroll
    for (int i = 0; i < 4; i++)
        #pragma unroll
        for (int q = 0; q < 4; q++) acc[i][q] = 0ull;

    for (int kt = 0; kt < K; kt += 16) {
        // A tile -> As[k][m]
        {
            const float* ap = Ab + (size_t)(m0 + am) * lda + kt + ak;
            float4 v0 = *(const float4*)ap;
            float4 v1 = *(const float4*)(ap + 4);
            As[(ak + 0) * 128 + am] = v0.x; As[(ak + 1) * 128 + am] = v0.y;
            As[(ak + 2) * 128 + am] = v0.z; As[(ak + 3) * 128 + am] = v0.w;
            As[(ak + 4) * 128 + am] = v1.x; As[(ak + 5) * 128 + am] = v1.y;
            As[(ak + 6) * 128 + am] = v1.z; As[(ak + 7) * 128 + am] = v1.w;
        }
        // B tile -> Bd[k][n] (dup)
        {
            int n = n0 + bn;
            float4 v = make_float4(0.f, 0.f, 0.f, 0.f);
            if (n < N) v = *(const float4*)(Bb + (size_t)n * ldb + kt + bk);
            Bd[(bk + 0) * 64 + bn] = pack2(v.x);
            Bd[(bk + 1) * 64 + bn] = pack2(v.y);
            Bd[(bk + 2) * 64 + bn] = pack2(v.z);
            Bd[(bk + 3) * 64 + bn] = pack2(v.w);
        }
        __syncthreads();

        #pragma unroll
        for (int k = 0; k < 16; k++) {
            ulonglong2 aA = *(const ulonglong2*)&As[k * 128 + ty * 8];
            ulonglong2 aB = *(const ulonglong2*)&As[k * 128 + ty * 8 + 4];
            ulonglong2 b0 = *(const ulonglong2*)&Bd[k * 64 + tx * 4];
            ulonglong2 b1 = *(const ulonglong2*)&Bd[k * 64 + tx * 4 + 2];
            fma2(acc[0][0], aA.x, b0.x); fma2(acc[0][1], aA.x, b0.y);
            fma2(acc[0][2], aA.x, b1.x); fma2(acc[0][3], aA.x, b1.y);
            fma2(acc[1][0], aA.y, b0.x); fma2(acc[1][1], aA.y, b0.y);
            fma2(acc[1][2], aA.y, b1.x); fma2(acc[1][3], aA.y, b1.y);
            fma2(acc[2][0], aB.x, b0.x); fma2(acc[2][1], aB.x, b0.y);
            fma2(acc[2][2], aB.x, b1.x); fma2(acc[2][3], aB.x, b1.y);
            fma2(acc[3][0], aB.y, b0.x); fma2(acc[3][1], aB.y, b0.y);
            fma2(acc[3][2], aB.y, b1.x); fma2(acc[3][3], aB.y, b1.y);
        }
        __syncthreads();
    }

    #pragma unroll
    for (int i = 0; i < 4; i++) {
        int m = m0 + ty * 8 + 2 * i;
        #pragma unroll
        for (int q = 0; q < 4; q++) {
            int n = n0 + tx * 4 + q;
            if (n < N) {
                float vlo, vhi;
                unpack2(acc[i][q], vlo, vhi);
                float bsum = 0.f;
                if (bias1) bsum += bias1[n];
                if (bias2) bsum += bias2[n];
                vlo += bsum; vhi += bsum;
                if (transC) {
                    Cb[((size_t)(m >> 5) * G4 + n) * BB + (m & 31)] = vlo;
                    Cb[((size_t)((m + 1) >> 5) * G4 + n) * BB + ((m + 1) & 31)] = vhi;
                } else {
                    Cb[(size_t)m * ldc + n] = vlo;
                    Cb[(size_t)(m + 1) * ldc + n] = vhi;
                }
            }
        }
    }
}

// ---------------- f32x2 SGEMM  C = A(MxK) * B(KxN) ------------------------------
__global__ __launch_bounds__(256)
void sgemm_nn2(const float* __restrict__ A, const float* __restrict__ B,
               float* __restrict__ C,
               int M, int N, int K, int lda, int ldb, int ldc,
               long long aBS, long long bBS, long long cBS)
{
    __shared__ float As[16 * 128];
    __shared__ ull   Bd[16 * 64];

    const int tid = threadIdx.x;
    const int tx = tid & 15;
    const int ty = tid >> 4;
    const int m0 = blockIdx.y * 128;
    const int n0 = blockIdx.x * 64;

    const float* Ab = A + (long long)blockIdx.z * aBS;
    const float* Bb = B + (long long)blockIdx.z * bBS;
    float*       Cb = C + (long long)blockIdx.z * cBS;

    const int am = tid >> 1;
    const int ak = (tid & 1) * 8;
    const int bkr = tid >> 4;           // 0..15 k row
    const int bnc = (tid & 15) * 4;     // n offset

    ull acc[4][4];
    #pragma unroll
    for (int i = 0; i < 4; i++)
        #pragma unroll
        for (int q = 0; q < 4; q++) acc[i][q] = 0ull;

    for (int kt = 0; kt < K; kt += 16) {
        {
            const float* ap = Ab + (size_t)(m0 + am) * lda + kt + ak;
            float4 v0 = *(const float4*)ap;
            float4 v1 = *(const float4*)(ap + 4);
            As[(ak + 0) * 128 + am] = v0.x; As[(ak + 1) * 128 + am] = v0.y;
            As[(ak + 2) * 128 + am] = v0.z; As[(ak + 3) * 128 + am] = v0.w;
            As[(ak + 4) * 128 + am] = v1.x; As[(ak + 5) * 128 + am] = v1.y;
            As[(ak + 6) * 128 + am] = v1.z; As[(ak + 7) * 128 + am] = v1.w;
        }
        {
            int n = n0 + bnc;
            float4 v = make_float4(0.f, 0.f, 0.f, 0.f);
            if (n < N) v = *(const float4*)(Bb + (size_t)(kt + bkr) * ldb + n);
            Bd[bkr * 64 + bnc + 0] = pack2(v.x);
            Bd[bkr * 64 + bnc + 1] = pack2(v.y);
            Bd[bkr * 64 + bnc + 2] = pack2(v.z);
            Bd[bkr * 64 + bnc + 3] = pack2(v.w);
        }
        __syncthreads();

        #pragma unroll
        for (int k = 0; k < 16; k++) {
            ulonglong2 aA = *(const ulonglong2*)&As[k * 128 + ty * 8];
            ulonglong2 aB = *(const ulonglong2*)&As[k * 128 + ty * 8 + 4];
            ulonglong2 b0 = *(const ulonglong2*)&Bd[k * 64 + tx * 4];
            ulonglong2 b1 = *(const ulonglong2*)&Bd[k * 64 + tx * 4 + 2];
            fma2(acc[0][0], aA.x, b0.x); fma2(acc[0][1], aA.x, b0.y);
            fma2(acc[0][2], aA.x, b1.x); fma2(acc[0][3], aA.x, b1.y);
            fma2(acc[1][0], aA.y, b0.x); fma2(acc[1][1], aA.y, b0.y);
            fma2(acc[1][2], aA.y, b1.x); fma2(acc[1][3], aA.y, b1.y);
            fma2(acc[2][0], aB.x, b0.x); fma2(acc[2][1], aB.x, b0.y);
            fma2(acc[2][2], aB.x, b1.x); fma2(acc[2][3], aB.x, b1.y);
            fma2(acc[3][0], aB.y, b0.x); fma2(acc[3][1], aB.y, b0.y);
            fma2(acc[3][2], aB.y, b1.x); fma2(acc[3][3], aB.y, b1.y);
        }
        __syncthreads();
    }

    #pragma unroll
    for (int i = 0; i < 4; i++) {
        int m = m0 + ty * 8 + 2 * i;
        #pragma unroll
        for (int q = 0; q < 4; q++) {
            int n = n0 + tx * 4 + q;
            if (n < N) {
                float vlo, vhi;
                unpack2(acc[i][q], vlo, vhi);
                Cb[(size_t)m * ldc + n] = vlo;
                Cb[(size_t)(m + 1) * ldc + n] = vhi;
            }
        }
    }
}

// ---------------- row softmax (in place) ----------------
__global__ __launch_bounds__(256)
void softmax_rows(float* __restrict__ data, int L)
{
    float* p = data + (size_t)blockIdx.x * L;
    __shared__ float red[256];
    const int tid = threadIdx.x;

    float m = -3.4e38f;
    for (int i = tid; i < L; i += 256) m = fmaxf(m, p[i]);
    red[tid] = m; __syncthreads();
    #pragma unroll
    for (int s = 128; s > 0; s >>= 1) {
        if (tid < s) red[tid] = fmaxf(red[tid], red[tid + s]);
        __syncthreads();
    }
    m = red[0]; __syncthreads();

    float sum = 0.f;
    for (int i = tid; i < L; i += 256) {
        float e = expf(p[i] - m);
        p[i] = e;
        sum += e;
    }
    red[tid] = sum; __syncthreads();
    #pragma unroll
    for (int s = 128; s > 0; s >>= 1) {
        if (tid < s) red[tid] += red[tid + s];
        __syncthreads();
    }
    const float inv = 1.f / red[0];
    for (int i = tid; i < L; i += 256) p[i] *= inv;
}

// ---------------- launch ----------------
extern "C" void kernel_launch(void* const* d_in, const int* in_sizes, int n_in,
                              void* d_out, int out_size)
{
    const float* inputs = (const float*)d_in[0];
    const float* h0     = (const float*)d_in[1];
    const float* c0     = (const float*)d_in[2];
    const float* Lst    = (const float*)d_in[3];
    const float* W_ih1  = (const float*)d_in[4];
    const float* W_hh1  = (const float*)d_in[5];
    const float* b_ih1  = (const float*)d_in[6];
    const float* b_hh1  = (const float*)d_in[7];
    const float* W_ih2  = (const float*)d_in[8];
    const float* W_hh2  = (const float*)d_in[9];
    const float* b_ih2  = (const float*)d_in[10];
    const float* b_hh2  = (const float*)d_in[11];
    const float* W_out  = (const float*)d_in[12];
    const float* b_out  = (const float*)d_in[13];
    float* out = (float*)d_out;

    void* p;
    cudaGetSymbolAddress(&p, g_X1);  float* X1  = (float*)p;
    cudaGetSymbolAddress(&p, g_H1);  float* H1  = (float*)p;
    cudaGetSymbolAddress(&p, g_S);   float* S   = (float*)p;
    cudaGetSymbolAddress(&p, g_CTX); float* CTX = (float*)p;
    cudaGetSymbolAddress(&p, g_X2);  float* X2  = (float*)p;
    cudaGetSymbolAddress(&p, g_HS);  float* HS  = (float*)p;

    cudaFuncSetAttribute(lstm_seq, cudaFuncAttributeMaxDynamicSharedMemorySize,
                         SMEM_LSTM);

    // X1 = inputs @ W_ih1^T + biases, stored [t][g4][b]
    {
        dim3 g(G4 / 64, (TT * BB) / 128, 1);
        sgemm_tn2<<<g, 256>>>(inputs, W_ih1, X1, b_ih1, b_hh1,
                              TT * BB, G4, EE, EE, EE, G4, 0, 0, 0, 1);
    }

    // layer-1 recurrence
    prep<<<1, 256>>>(h0);
    lstm_seq<<<NBLK, 256, SMEM_LSTM>>>(X1, W_hh1, c0, H1);

    // attention: S[t,b,u] = sum_h H1[t,b,h] * L[u,b,h]
    {
        dim3 g(UU / 64, TT / 128, BB);
        sgemm_tn2<<<g, 256>>>(H1, Lst, S, nullptr, nullptr,
                              TT, UU, HH, BB * HH, BB * HH, BB * UU,
                              HH, HH, UU, 0);
    }
    softmax_rows<<<TT * BB, 256>>>(S, UU);
    // CTX[t,b,h] = sum_u S[t,b,u] * L[u,b,h]
    {
        dim3 g(HH / 64, TT / 128, BB);
        sgemm_nn2<<<g, 256>>>(S, Lst, CTX,
                              TT, HH, UU, BB * UU, BB * HH, BB * HH,
                              UU, HH, HH);
    }

    // X2 = CTX @ W_ih2^T + biases, stored [t][g4][b]
    {
        dim3 g(G4 / 64, (TT * BB) / 128, 1);
        sgemm_tn2<<<g, 256>>>(CTX, W_ih2, X2, b_ih2, b_hh2,
                              TT * BB, G4, HH, HH, HH, G4, 0, 0, 0, 1);
    }

    // layer-2 recurrence
    prep<<<1, 256>>>(h0 + BB * HH);
    lstm_seq<<<NBLK, 256, SMEM_LSTM>>>(X2, W_hh2, c0 + BB * HH, HS);

    // logits = HS @ W_out^T + b_out -> softmax over V
    {
        dim3 g((VV + 63) / 64, (TT * BB) / 128, 1);
        sgemm_tn2<<<g, 256>>>(HS, W_out, out, b_out, nullptr,
                              TT * BB, VV, HH, HH, HH, VV, 0, 0, 0, 0);
    }
    softmax_rows<<<TT * BB, 256>>>(out, VV);
}

// round 9
// speedup vs baseline: 1.3764x; 1.3764x over previous
#include <cuda_runtime.h>
#include <math.h>

#define TT 128
#define BB 32
#define EE 512
#define HH 512
#define UU 1024
#define VV 10000
#define G4 2048   // 4*H

// recurrence: 32 h-col tiles (16 cols) x 4 batch groups (8 b)   [R6 design]
#define NBLK 128
#define SMEM_LSTM (131072 + 32768 + 16384)   // Wt + hsd + Pp = 176KB

// ---------------- scratch (static device globals; no allocation) ----------------
__device__ __align__(128) float g_X1 [TT*G4*BB];   // pregates [t][g4][b]
__device__ __align__(128) float g_H1 [TT*BB*HH];
__device__ __align__(128) float g_S  [TT*BB*UU];
__device__ __align__(128) float g_CTX[TT*BB*HH];
__device__ __align__(128) float g_X2 [TT*G4*BB];   // pregates [t][g4][b]
__device__ __align__(128) float g_HS [TT*BB*HH];
__device__ __align__(128) float g_HT [2][4*512*8]; // parity h [bg][k][b8]
__device__ unsigned g_flag[NBLK];                  // [bg*32 + hc], monotonic

// ---------------- helpers ----------------
typedef unsigned long long ull;
__device__ __forceinline__ ull pack2(float x) {
    ull r;
    asm("mov.b64 %0, {%1, %1};" : "=l"(r) : "r"(__float_as_uint(x)));
    return r;
}
__device__ __forceinline__ void fma2(ull& d, ull a, ull b) {
    asm("fma.rn.f32x2 %0, %1, %2, %0;" : "+l"(d) : "l"(a), "l"(b));
}
__device__ __forceinline__ unsigned ld_acq(const unsigned* p) {
    unsigned v;
    asm volatile("ld.acquire.gpu.global.u32 %0, [%1];" : "=r"(v) : "l"(p));
    return v;
}
__device__ __forceinline__ void st_rel(unsigned* p, unsigned v) {
    asm volatile("st.release.gpu.global.u32 [%0], %1;" :: "l"(p), "r"(v) : "memory");
}
__device__ __forceinline__ float sigmoidf_(float x) { return 1.f / (1.f + expf(-x)); }

__device__ __forceinline__ unsigned f2tf32(float f) {
    unsigned u;
    asm("cvt.rna.tf32.f32 %0, %1;" : "=r"(u) : "f"(f));
    return u;
}

// ---------------- prep: reset flags, h0 -> g_HT[1] in [bg][k][b8] layout --------
__global__ void prep(const float* __restrict__ h0row)
{
    int tid = threadIdx.x;
    if (tid < NBLK) g_flag[tid] = 0;
    for (int idx = tid; idx < BB * HH; idx += 256) {
        int b = idx >> 9, h = idx & 511;
        g_HT[1][(b >> 3) * 4096 + h * 8 + (b & 7)] = h0row[idx];
    }
}

// ---------------- persistent LSTM recurrence (R6, best) -------------------------
__global__ __launch_bounds__(256)
void lstm_seq(const float* __restrict__ XT,     // [T][G4][B] pregates
              const float* __restrict__ Whh,    // [G4][H]
              const float* __restrict__ c0row,  // [B][H]
              float* __restrict__ Hout)         // [T][B][H]
{
    extern __shared__ char smraw[];
    float* Wt  = (float*)smraw;                   // [512][64]
    ull*   hsd = (ull*)(smraw + 131072);          // [512][8] dup h
    ull*   Pp  = (ull*)(smraw + 131072 + 32768);  // [8][32][8] partials

    const int bid = blockIdx.x;
    const int tid = threadIdx.x;
    const int hc  = bid & 31;
    const int bg  = bid >> 5;

    for (int idx = tid; idx < 64 * 128; idx += 256) {
        int r  = idx & 63;
        int k4 = idx >> 6;
        int g = r >> 4, j = r & 15;
        int gr = g * 512 + 16 * hc + j;
        float4 w = *(const float4*)(Whh + (size_t)gr * HH + k4 * 4);
        Wt[(k4 * 4 + 0) * 64 + r] = w.x;
        Wt[(k4 * 4 + 1) * 64 + r] = w.y;
        Wt[(k4 * 4 + 2) * 64 + r] = w.z;
        Wt[(k4 * 4 + 3) * 64 + r] = w.w;
    }

    const int warp = tid >> 5;
    const int lane = tid & 31;
    const int rg   = lane >> 1;
    const int bq   = lane & 1;
    const int kbeg = warp * 64;

    const int j  = tid >> 3;
    const int bb = tid & 7;
    float cv = 0.f;
    if (tid < 128) cv = c0row[(8 * bg + bb) * HH + 16 * hc + j];

    unsigned* myflag = &g_flag[bid];
    const unsigned* grpflags = &g_flag[bg * 32];

    for (int t = 0; t < TT; t++) {
        if (t > 0) {
            if (tid < 32) {
                const unsigned* f = grpflags + tid;
                while (ld_acq(f) < (unsigned)t) { }
            }
        }
        __syncthreads();

        {
            const float4* src = (const float4*)&g_HT[(t + 1) & 1][bg * 4096];
            #pragma unroll
            for (int r = 0; r < 4; r++) {
                int i = tid + r * 256;
                float4 v = __ldcg(src + i);
                int k  = i >> 1;
                int b0 = (i & 1) * 4;
                ull* d = &hsd[k * 8 + b0];
                d[0] = pack2(v.x); d[1] = pack2(v.y);
                d[2] = pack2(v.z); d[3] = pack2(v.w);
            }
        }
        __syncthreads();

        ull acc[2][4];
        #pragma unroll
        for (int i = 0; i < 2; i++)
            #pragma unroll
            for (int q = 0; q < 4; q++) acc[i][q] = 0ull;

        #pragma unroll 4
        for (int k = kbeg; k < kbeg + 64; k++) {
            ulonglong2 wp = *(const ulonglong2*)&Wt[k * 64 + rg * 4];
            ulonglong2 hA = *(const ulonglong2*)&hsd[k * 8 + bq * 4];
            ulonglong2 hB = *(const ulonglong2*)&hsd[k * 8 + bq * 4 + 2];
            fma2(acc[0][0], wp.x, hA.x); fma2(acc[0][1], wp.x, hA.y);
            fma2(acc[0][2], wp.x, hB.x); fma2(acc[0][3], wp.x, hB.y);
            fma2(acc[1][0], wp.y, hA.x); fma2(acc[1][1], wp.y, hA.y);
            fma2(acc[1][2], wp.y, hB.x); fma2(acc[1][3], wp.y, hB.y);
        }

        {
            ull* pb = &Pp[((warp * 32) + rg * 2) * 8 + bq * 4];
            *(ulonglong2*)(pb + 0)  = make_ulonglong2(acc[0][0], acc[0][1]);
            *(ulonglong2*)(pb + 2)  = make_ulonglong2(acc[0][2], acc[0][3]);
            *(ulonglong2*)(pb + 8)  = make_ulonglong2(acc[1][0], acc[1][1]);
            *(ulonglong2*)(pb + 10) = make_ulonglong2(acc[1][2], acc[1][3]);
        }
        __syncthreads();

        if (tid < 128) {
            const float* pf = (const float*)Pp;
            float gate[4];
            #pragma unroll
            for (int g = 0; g < 4; g++) {
                int r  = g * 16 + j;
                int rp = r >> 1, ln = r & 1;
                float v = XT[((size_t)t * G4 + g * 512 + 16 * hc + j) * BB
                             + 8 * bg + bb];
                #pragma unroll
                for (int s = 0; s < 8; s++)
                    v += pf[((s * 32 + rp) * 8 + bb) * 2 + ln];
                gate[g] = v;
            }
            float gi = sigmoidf_(gate[0]);
            float gf = sigmoidf_(gate[1]);
            float gg = tanhf(gate[2]);
            float go = sigmoidf_(gate[3]);
            cv = gf * cv + gi * gg;
            float hv = go * tanhf(cv);
            Hout[(size_t)t * BB * HH + (8 * bg + bb) * HH + 16 * hc + j] = hv;
            g_HT[t & 1][bg * 4096 + (16 * hc + j) * 8 + bb] = hv;
        }

        __syncthreads();
        if (tid == 0) st_rel(myflag, (unsigned)(t + 1));
    }
}

// ---------------- tf32x3 tensor-core GEMM  C = A(MxK) * B(NxK)^T + biases -------
// Block 64m x 64n, 128 threads (4 warps, 2x2), warp tile 32m x 32n.
// mma.m16n8k8.tf32, 3xTF32 compensation (hi*hi + hi*lo + lo*hi) ~ fp32 accuracy.
// transC=1: store C[(m>>5)][n][m&31] ([t][g4][b]).
#define TPAD 20
__global__ __launch_bounds__(128)
void gemm_tn_tf32(const float* __restrict__ A, const float* __restrict__ B,
                  float* __restrict__ C,
                  const float* __restrict__ bias1, const float* __restrict__ bias2,
                  int M, int N, int K, int lda, int ldb, int ldc,
                  long long aBS, long long bBS, long long cBS, int transC)
{
    __shared__ float Ah[64 * TPAD], Al[64 * TPAD];
    __shared__ float Bh[64 * TPAD], Bl[64 * TPAD];

    const int tid  = threadIdx.x;
    const int warp = tid >> 5;
    const int lane = tid & 31;
    const int wm = warp >> 1;        // 0..1
    const int wn = warp & 1;         // 0..1
    const int gq  = lane >> 2;       // group id 0..7
    const int tig = lane & 3;        // thread-in-group

    const int m0 = blockIdx.y * 64;
    const int n0 = blockIdx.x * 64;

    const float* Ab = A + (long long)blockIdx.z * aBS;
    const float* Bb = B + (long long)blockIdx.z * bBS;
    float*       Cb = C + (long long)blockIdx.z * cBS;

    const int lrow  = tid >> 1;          // 0..63
    const int lpart = (tid & 1) * 8;     // 0 / 8

    float c[2][4][4];
    #pragma unroll
    for (int ta = 0; ta < 2; ta++)
        #pragma unroll
        for (int tb = 0; tb < 4; tb++)
            #pragma unroll
            for (int q = 0; q < 4; q++) c[ta][tb][q] = 0.f;

    for (int kt = 0; kt < K; kt += 16) {
        // ---- stage A (64 x 16) split hi/lo ----
        {
            const float* ap = Ab + (size_t)(m0 + lrow) * lda + kt + lpart;
            float v[8];
            *(float4*)&v[0] = *(const float4*)ap;
            *(float4*)&v[4] = *(const float4*)(ap + 4);
            float hi[8], lo[8];
            #pragma unroll
            for (int q = 0; q < 8; q++) {
                hi[q] = __uint_as_float(f2tf32(v[q]));
                lo[q] = __uint_as_float(f2tf32(v[q] - hi[q]));
            }
            float* dh = &Ah[lrow * TPAD + lpart];
            float* dl = &Al[lrow * TPAD + lpart];
            *(float4*)dh = *(float4*)&hi[0]; *(float4*)(dh + 4) = *(float4*)&hi[4];
            *(float4*)dl = *(float4*)&lo[0]; *(float4*)(dl + 4) = *(float4*)&lo[4];
        }
        // ---- stage B (64 x 16) split hi/lo, n-guarded ----
        {
            int n = n0 + lrow;
            float v[8];
            if (n < N) {
                const float* bp = Bb + (size_t)n * ldb + kt + lpart;
                *(float4*)&v[0] = *(const float4*)bp;
                *(float4*)&v[4] = *(const float4*)(bp + 4);
            } else {
                #pragma unroll
                for (int q = 0; q < 8; q++) v[q] = 0.f;
            }
            float hi[8], lo[8];
            #pragma unroll
            for (int q = 0; q < 8; q++) {
                hi[q] = __uint_as_float(f2tf32(v[q]));
                lo[q] = __uint_as_float(f2tf32(v[q] - hi[q]));
            }
            float* dh = &Bh[lrow * TPAD + lpart];
            float* dl = &Bl[lrow * TPAD + lpart];
            *(float4*)dh = *(float4*)&hi[0]; *(float4*)(dh + 4) = *(float4*)&hi[4];
            *(float4*)dl = *(float4*)&lo[0]; *(float4*)(dl + 4) = *(float4*)&lo[4];
        }
        __syncthreads();

        #pragma unroll
        for (int k8 = 0; k8 < 16; k8 += 8) {
            unsigned ah[2][4], al[2][4], bh[4][2], bl[4][2];
            #pragma unroll
            for (int ta = 0; ta < 2; ta++) {
                int base = (wm * 32 + ta * 16 + gq) * TPAD + k8 + tig;
                ah[ta][0] = __float_as_uint(Ah[base]);
                ah[ta][1] = __float_as_uint(Ah[base + 8 * TPAD]);
                ah[ta][2] = __float_as_uint(Ah[base + 4]);
                ah[ta][3] = __float_as_uint(Ah[base + 8 * TPAD + 4]);
                al[ta][0] = __float_as_uint(Al[base]);
                al[ta][1] = __float_as_uint(Al[base + 8 * TPAD]);
                al[ta][2] = __float_as_uint(Al[base + 4]);
                al[ta][3] = __float_as_uint(Al[base + 8 * TPAD + 4]);
            }
            #pragma unroll
            for (int tb = 0; tb < 4; tb++) {
                int base = (wn * 32 + tb * 8 + gq) * TPAD + k8 + tig;
                bh[tb][0] = __float_as_uint(Bh[base]);
                bh[tb][1] = __float_as_uint(Bh[base + 4]);
                bl[tb][0] = __float_as_uint(Bl[base]);
                bl[tb][1] = __float_as_uint(Bl[base + 4]);
            }
            #pragma unroll
            for (int ta = 0; ta < 2; ta++)
                #pragma unroll
                for (int tb = 0; tb < 4; tb++) {
                    float* cc = c[ta][tb];
                    asm volatile(
                        "mma.sync.aligned.m16n8k8.row.col.f32.tf32.tf32.f32 "
                        "{%0,%1,%2,%3}, {%4,%5,%6,%7}, {%8,%9}, {%0,%1,%2,%3};"
                        : "+f"(cc[0]), "+f"(cc[1]), "+f"(cc[2]), "+f"(cc[3])
                        : "r"(ah[ta][0]), "r"(ah[ta][1]), "r"(ah[ta][2]), "r"(ah[ta][3]),
                          "r"(bh[tb][0]), "r"(bh[tb][1]));
                    asm volatile(
                        "mma.sync.aligned.m16n8k8.row.col.f32.tf32.tf32.f32 "
                        "{%0,%1,%2,%3}, {%4,%5,%6,%7}, {%8,%9}, {%0,%1,%2,%3};"
                        : "+f"(cc[0]), "+f"(cc[1]), "+f"(cc[2]), "+f"(cc[3])
                        : "r"(ah[ta][0]), "r"(ah[ta][1]), "r"(ah[ta][2]), "r"(ah[ta][3]),
                          "r"(bl[tb][0]), "r"(bl[tb][1]));
                    asm volatile(
                        "mma.sync.aligned.m16n8k8.row.col.f32.tf32.tf32.f32 "
                        "{%0,%1,%2,%3}, {%4,%5,%6,%7}, {%8,%9}, {%0,%1,%2,%3};"
                        : "+f"(cc[0]), "+f"(cc[1]), "+f"(cc[2]), "+f"(cc[3])
                        : "r"(al[ta][0]), "r"(al[ta][1]), "r"(al[ta][2]), "r"(al[ta][3]),
                          "r"(bh[tb][0]), "r"(bh[tb][1]));
                }
        }
        __syncthreads();
    }

    // ---- epilogue ----
    #pragma unroll
    for (int ta = 0; ta < 2; ta++) {
        int mrow = m0 + wm * 32 + ta * 16 + gq;
        #pragma unroll
        for (int tb = 0; tb < 4; tb++) {
            int ncol = n0 + wn * 32 + tb * 8 + 2 * tig;
            #pragma unroll
            for (int half = 0; half < 2; half++) {     // c rows mrow, mrow+8
                int m = mrow + half * 8;
                #pragma unroll
                for (int q = 0; q < 2; q++) {          // cols ncol, ncol+1
                    int n = ncol + q;
                    if (n < N) {
                        float v = c[ta][tb][half * 2 + q];
                        if (bias1) v += bias1[n];
                        if (bias2) v += bias2[n];
                        if (transC)
                            Cb[((size_t)(m >> 5) * G4 + n) * BB + (m & 31)] = v;
                        else
                            Cb[(size_t)m * ldc + n] = v;
                    }
                }
            }
        }
    }
}

// ---------------- SGEMM  C = A(MxK) * B(KxN)  (scalar, R6) ----------------------
__global__ __launch_bounds__(256)
void sgemm_nn(const float* __restrict__ A, const float* __restrict__ B,
              float* __restrict__ C,
              int M, int N, int K, int lda, int ldb, int ldc,
              long long aBS, long long bBS, long long cBS)
{
    __shared__ float As[16][64];
    __shared__ float Bs[16][64];

    const int tid = threadIdx.x;
    const int tx = tid & 15;
    const int ty = tid >> 4;
    const int m0 = blockIdx.y * 64;
    const int n0 = blockIdx.x * 64;

    const float* Ab = A + (long long)blockIdx.z * aBS;
    const float* Bb = B + (long long)blockIdx.z * bBS;
    float*       Cb = C + (long long)blockIdx.z * cBS;

    const int lr = tid >> 2;
    const int lk = (tid & 3) << 2;
    const int bkr = tid >> 4;
    const int bnc = (tid & 15) << 2;

    float acc[4][4];
    #pragma unroll
    for (int i = 0; i < 4; i++)
        #pragma unroll
        for (int q = 0; q < 4; q++) acc[i][q] = 0.f;

    for (int kt = 0; kt < K; kt += 16) {
        {
            int m = m0 + lr;
            float4 v = make_float4(0.f, 0.f, 0.f, 0.f);
            if (m < M) v = *(const float4*)(Ab + (size_t)m * lda + kt + lk);
            As[lk + 0][lr] = v.x; As[lk + 1][lr] = v.y;
            As[lk + 2][lr] = v.z; As[lk + 3][lr] = v.w;
        }
        {
            int n = n0 + bnc;
            float4 v = make_float4(0.f, 0.f, 0.f, 0.f);
            if (n < N) v = *(const float4*)(Bb + (size_t)(kt + bkr) * ldb + n);
            *(float4*)&Bs[bkr][bnc] = v;
        }
        __syncthreads();
        #pragma unroll
        for (int k = 0; k < 16; k++) {
            float a[4], b[4];
            *(float4*)a = *(const float4*)&As[k][ty << 2];
            *(float4*)b = *(const float4*)&Bs[k][tx << 2];
            #pragma unroll
            for (int i = 0; i < 4; i++)
                #pragma unroll
                for (int q = 0; q < 4; q++)
                    acc[i][q] += a[i] * b[q];
        }
        __syncthreads();
    }

    #pragma unroll
    for (int i = 0; i < 4; i++) {
        int m = m0 + (ty << 2) + i;
        if (m >= M) continue;
        #pragma unroll
        for (int q = 0; q < 4; q++) {
            int n = n0 + (tx << 2) + q;
            if (n < N) Cb[(size_t)m * ldc + n] = acc[i][q];
        }
    }
}

// ---------------- row softmax (in place) ----------------
__global__ __launch_bounds__(256)
void softmax_rows(float* __restrict__ data, int L)
{
    float* p = data + (size_t)blockIdx.x * L;
    __shared__ float red[256];
    const int tid = threadIdx.x;

    float m = -3.4e38f;
    for (int i = tid; i < L; i += 256) m = fmaxf(m, p[i]);
    red[tid] = m; __syncthreads();
    #pragma unroll
    for (int s = 128; s > 0; s >>= 1) {
        if (tid < s) red[tid] = fmaxf(red[tid], red[tid + s]);
        __syncthreads();
    }
    m = red[0]; __syncthreads();

    float sum = 0.f;
    for (int i = tid; i < L; i += 256) {
        float e = expf(p[i] - m);
        p[i] = e;
        sum += e;
    }
    red[tid] = sum; __syncthreads();
    #pragma unroll
    for (int s = 128; s > 0; s >>= 1) {
        if (tid < s) red[tid] += red[tid + s];
        __syncthreads();
    }
    const float inv = 1.f / red[0];
    for (int i = tid; i < L; i += 256) p[i] *= inv;
}

// ---------------- launch ----------------
extern "C" void kernel_launch(void* const* d_in, const int* in_sizes, int n_in,
                              void* d_out, int out_size)
{
    const float* inputs = (const float*)d_in[0];
    const float* h0     = (const float*)d_in[1];
    const float* c0     = (const float*)d_in[2];
    const float* Lst    = (const float*)d_in[3];
    const float* W_ih1  = (const float*)d_in[4];
    const float* W_hh1  = (const float*)d_in[5];
    const float* b_ih1  = (const float*)d_in[6];
    const float* b_hh1  = (const float*)d_in[7];
    const float* W_ih2  = (const float*)d_in[8];
    const float* W_hh2  = (const float*)d_in[9];
    const float* b_ih2  = (const float*)d_in[10];
    const float* b_hh2  = (const float*)d_in[11];
    const float* W_out  = (const float*)d_in[12];
    const float* b_out  = (const float*)d_in[13];
    float* out = (float*)d_out;

    void* p;
    cudaGetSymbolAddress(&p, g_X1);  float* X1  = (float*)p;
    cudaGetSymbolAddress(&p, g_H1);  float* H1  = (float*)p;
    cudaGetSymbolAddress(&p, g_S);   float* S   = (float*)p;
    cudaGetSymbolAddress(&p, g_CTX); float* CTX = (float*)p;
    cudaGetSymbolAddress(&p, g_X2);  float* X2  = (float*)p;
    cudaGetSymbolAddress(&p, g_HS);  float* HS  = (float*)p;

    cudaFuncSetAttribute(lstm_seq, cudaFuncAttributeMaxDynamicSharedMemorySize,
                         SMEM_LSTM);

    // X1 = inputs @ W_ih1^T + biases, stored [t][g4][b]
    {
        dim3 g(G4 / 64, (TT * BB) / 64, 1);
        gemm_tn_tf32<<<g, 128>>>(inputs, W_ih1, X1, b_ih1, b_hh1,
                                 TT * BB, G4, EE, EE, EE, G4, 0, 0, 0, 1);
    }

    // layer-1 recurrence
    prep<<<1, 256>>>(h0);
    lstm_seq<<<NBLK, 256, SMEM_LSTM>>>(X1, W_hh1, c0, H1);

    // attention: S[t,b,u] = sum_h H1[t,b,h] * L[u,b,h]
    {
        dim3 g(UU / 64, TT / 64, BB);
        gemm_tn_tf32<<<g, 128>>>(H1, Lst, S, nullptr, nullptr,
                                 TT, UU, HH, BB * HH, BB * HH, BB * UU,
                                 HH, HH, UU, 0);
    }
    softmax_rows<<<TT * BB, 256>>>(S, UU);
    // CTX[t,b,h] = sum_u S[t,b,u] * L[u,b,h]
    {
        dim3 g(HH / 64, TT / 64, BB);
        sgemm_nn<<<g, 256>>>(S, Lst, CTX,
                             TT, HH, UU, BB * UU, BB * HH, BB * HH,
                             UU, HH, HH);
    }

    // X2 = CTX @ W_ih2^T + biases, stored [t][g4][b]
    {
        dim3 g(G4 / 64, (TT * BB) / 64, 1);
        gemm_tn_tf32<<<g, 128>>>(CTX, W_ih2, X2, b_ih2, b_hh2,
                                 TT * BB, G4, HH, HH, HH, G4, 0, 0, 0, 1);
    }

    // layer-2 recurrence
    prep<<<1, 256>>>(h0 + BB * HH);
    lstm_seq<<<NBLK, 256, SMEM_LSTM>>>(X2, W_hh2, c0 + BB * HH, HS);

    // logits = HS @ W_out^T + b_out -> softmax over V
    {
        dim3 g((VV + 63) / 64, (TT * BB) / 64, 1);
        gemm_tn_tf32<<<g, 128>>>(HS, W_out, out, b_out, nullptr,
                                 TT * BB, VV, HH, HH, HH, VV, 0, 0, 0, 0);
    }
    softmax_rows<<<TT * BB, 256>>>(out, VV);
}